// round 2
// baseline (speedup 1.0000x reference)
#include <cuda_runtime.h>
#include <cstdint>

// out[e, 0:128]   = node_states[src[e], :]
// out[e, 128:256] = node_states[tgt[e], :]
// One warp per edge. Each lane copies one float4 of each half.
// D_FEAT = 128 floats = 32 float4 per row half.
//
// NOTE: reference declares int64 indices, but JAX default config truncates
// to int32 — the device buffers are int32 (R1 illegal-access post-mortem).

__global__ __launch_bounds__(256) void node_propagate_kernel(
    const float4* __restrict__ ns,   // [N_NODES, 32] as float4
    const int* __restrict__ src,     // [E] int32
    const int* __restrict__ tgt,     // [E] int32
    float4* __restrict__ out,        // [E, 64] as float4
    int E)
{
    const int gwarp = (int)((blockIdx.x * (unsigned)blockDim.x + threadIdx.x) >> 5);
    const int lane  = threadIdx.x & 31;
    if (gwarp >= E) return;

    // Broadcast index loads (all lanes same address -> 1 transaction each)
    const int s = __ldg(&src[gwarp]);
    const int t = __ldg(&tgt[gwarp]);

    // Gather reads: node_states is 5.12 MB -> L2-resident after first touch.
    const float4 a = __ldg(&ns[(size_t)s * 32 + lane]);
    const float4 b = __ldg(&ns[(size_t)t * 32 + lane]);

    // Streaming stores: 328 MB write stream; keep it out of L2's way.
    float4* o = out + (size_t)gwarp * 64;
    __stcs(o + lane, a);
    __stcs(o + 32 + lane, b);
}

extern "C" void kernel_launch(void* const* d_in, const int* in_sizes, int n_in,
                              void* d_out, int out_size)
{
    const float4* ns  = (const float4*)d_in[0];
    const int*    src = (const int*)d_in[1];
    const int*    tgt = (const int*)d_in[2];
    float4*       out = (float4*)d_out;

    const int E = in_sizes[1];  // 320000 edges

    const int threads = 256;    // 8 warps -> 8 edges per block
    const int blocks  = (E * 32 + threads - 1) / threads;

    node_propagate_kernel<<<blocks, threads>>>(ns, src, tgt, out, E);
}

// round 3
// speedup vs baseline: 1.0413x; 1.0413x over previous
#include <cuda_runtime.h>
#include <cstdint>

// out[e, 0:128]   = node_states[src[e], :]
// out[e, 128:256] = node_states[tgt[e], :]
// One warp per TWO edges: 4 independent row-gathers in flight (MLP=4),
// single int2 load for each index pair. D=128 floats = 32 float4/row.
// Steady-state binder is the 328 MB DRAM write stream (~79% of spec at
// 51.7us); this round targets issue/latency overhead on top of it.

__global__ __launch_bounds__(256) void node_propagate_kernel(
    const float4* __restrict__ ns,   // [N_NODES, 32] as float4
    const int* __restrict__ src,     // [E] int32
    const int* __restrict__ tgt,     // [E] int32
    float4* __restrict__ out,        // [E, 64] as float4
    int E)
{
    const int gwarp = (int)((blockIdx.x * (unsigned)blockDim.x + threadIdx.x) >> 5);
    const int lane  = threadIdx.x & 31;
    const int e0    = gwarp * 2;
    if (e0 >= E) return;
    const bool two = (e0 + 1 < E);

    // Index pairs: adjacent int32s -> one 8B broadcast load each.
    int2 s2, t2;
    if (two) {
        s2 = *(const int2*)(src + e0);
        t2 = *(const int2*)(tgt + e0);
    } else {
        s2 = make_int2(__ldg(&src[e0]), 0);
        t2 = make_int2(__ldg(&tgt[e0]), 0);
    }

    // 4 independent gathers in flight (node_states is L2-resident, 5.12 MB).
    const float4 a0 = __ldg(&ns[(size_t)s2.x * 32 + lane]);
    const float4 b0 = __ldg(&ns[(size_t)t2.x * 32 + lane]);
    float4 a1, b1;
    if (two) {
        a1 = __ldg(&ns[(size_t)s2.y * 32 + lane]);
        b1 = __ldg(&ns[(size_t)t2.y * 32 + lane]);
    }

    // Streaming stores: evict-first keeps node_states resident in L2.
    float4* o = out + (size_t)e0 * 64;
    __stcs(o + lane,      a0);
    __stcs(o + 32 + lane, b0);
    if (two) {
        __stcs(o + 64 + lane, a1);
        __stcs(o + 96 + lane, b1);
    }
}

extern "C" void kernel_launch(void* const* d_in, const int* in_sizes, int n_in,
                              void* d_out, int out_size)
{
    const float4* ns  = (const float4*)d_in[0];
    const int*    src = (const int*)d_in[1];
    const int*    tgt = (const int*)d_in[2];
    float4*       out = (float4*)d_out;

    const int E = in_sizes[1];  // 320000 edges

    const int threads = 256;                    // 8 warps -> 16 edges per block
    const int warps   = (E + 1) / 2;
    const int blocks  = (warps * 32 + threads - 1) / threads;

    node_propagate_kernel<<<blocks, threads>>>(ns, src, tgt, out, E);
}